// round 3
// baseline (speedup 1.0000x reference)
#include <cuda_runtime.h>

// MultiScaleProcessor: input [64,256,256,3] f32 -> output [64,4,256,256,3] f32
// scales = {32,64,128,256}; bilinear (linspace endpoints), zero-pad to 256.
//
// 1-D grid, explicitly ordered: compute chunks first (long latency), then
// copy chunks, then zero chunks (pure store BW) to fill the tail.

#define HH 256
#define WW 256
#define NB 64
#define ROWF (WW * 3)         // 768 floats per row
#define CHUNK 8               // rows per block; pads (112,96,64) are %8==0
#define CROWV (CHUNK * ROWF / 4)  // 1536 float4 per chunk
#define NT 256
#define VPT (CROWV / NT)      // 6 float4 per thread
#define PPT (CHUNK * WW / NT) // 8 pixels per thread (compute path)

#define N_COMP_PER_B 28       // 4 (s=32) + 8 (s=64) + 16 (s=128)
#define N_COPY_PER_B 32       // s=256
#define N_ZERO_PER_B 68
#define N_COMP (NB * N_COMP_PER_B)   // 1792
#define N_COPY (NB * N_COPY_PER_B)   // 2048
#define N_ZERO (NB * N_ZERO_PER_B)   // 4352

__global__ __launch_bounds__(NT) void msp_kernel(const float* __restrict__ in,
                                                 float* __restrict__ out) {
    const int bid = blockIdx.x;
    const int tid = threadIdx.x;

    int b, sc, cy;  // batch, scale index, chunk row index (0..31)

    if (bid < N_COMP) {
        // ---- compute chunks: scheduled FIRST (stragglers) ----
        b = bid / N_COMP_PER_B;
        const int k = bid % N_COMP_PER_B;
        if (k < 4)       { sc = 0; cy = 14 + k; }        // s=32,  p=112 -> rows 112..143
        else if (k < 12) { sc = 1; cy = 12 + (k - 4); }  // s=64,  p=96  -> rows 96..159
        else             { sc = 2; cy = 8 + (k - 12); }  // s=128, p=64  -> rows 64..191
    } else if (bid < N_COMP + N_COPY) {
        // ---- copy chunks (s=256) ----
        const int i = bid - N_COMP;
        b = i / N_COPY_PER_B;
        cy = i % N_COPY_PER_B;
        const int yc = cy * CHUNK;
        float4* __restrict__ ochunk =
            (float4*)(out + ((((size_t)b * 4 + 3) * HH + yc) * ROWF));
        const float4* __restrict__ ichunk =
            (const float4*)(in + ((size_t)b * HH + yc) * ROWF);
#pragma unroll
        for (int i2 = 0; i2 < VPT; i2++)
            __stcs(&ochunk[tid + i2 * NT], __ldg(&ichunk[tid + i2 * NT]));
        return;
    } else {
        // ---- zero chunks: scheduled LAST (pure store BW, fill the tail) ----
        const int i = bid - N_COMP - N_COPY;
        b = i / N_ZERO_PER_B;
        const int k = i % N_ZERO_PER_B;
        if (k < 14)      { sc = 0; cy = k; }             // s=32 top pad
        else if (k < 28) { sc = 0; cy = (k - 14) + 18; } // s=32 bottom pad
        else if (k < 40) { sc = 1; cy = (k - 28); }      // s=64 top pad
        else if (k < 52) { sc = 1; cy = (k - 40) + 20; } // s=64 bottom pad
        else if (k < 60) { sc = 2; cy = (k - 52); }      // s=128 top pad
        else             { sc = 2; cy = (k - 60) + 24; } // s=128 bottom pad
        const int yc = cy * CHUNK;
        float4* __restrict__ ochunk =
            (float4*)(out + ((((size_t)b * 4 + sc) * HH + yc) * ROWF));
        const float4 z = make_float4(0.f, 0.f, 0.f, 0.f);
#pragma unroll
        for (int i2 = 0; i2 < VPT; i2++)
            __stcs(&ochunk[tid + i2 * NT], z);
        return;
    }

    // ---- compute path: bilinear 8 rows into shared, vectorized flush ----
    const int s  = 32 << sc;
    const int p  = (256 - s) >> 1;
    const int yc = cy * CHUNK;

    __shared__ __align__(16) float rows[CHUNK * ROWF];

    const float inv = 255.0f / (float)(s - 1);
    const float* __restrict__ base = in + (size_t)b * (HH * ROWF);

#pragma unroll
    for (int i = 0; i < PPT; i++) {
        const int pi = tid + i * NT;   // 0..2047
        const int r  = pi >> 8;        // local row 0..7
        const int x  = pi & 255;       // column 0..255
        float* dst = &rows[r * ROWF + 3 * x];
        if (x < p || x >= p + s) {
            dst[0] = 0.f; dst[1] = 0.f; dst[2] = 0.f;
        } else {
            const int   y  = yc + r - p;
            const float fy = (float)y * inv;
            const int   y0 = (int)fy;          // fy >= 0: trunc == floor
            const int   y1 = min(y0 + 1, HH - 1);
            const float wy = fy - (float)y0;

            const float fx = (float)(x - p) * inv;
            const int   x0 = (int)fx;
            const int   x1 = min(x0 + 1, WW - 1);
            const float wx = fx - (float)x0;

            const float* __restrict__ r0 = base + (size_t)y0 * ROWF;
            const float* __restrict__ r1 = base + (size_t)y1 * ROWF;
            const float wx0 = 1.f - wx;
            const float wy0 = 1.f - wy;
#pragma unroll
            for (int c = 0; c < 3; c++) {
                const float t  = __ldg(r0 + 3 * x0 + c) * wx0 +
                                 __ldg(r0 + 3 * x1 + c) * wx;
                const float bt = __ldg(r1 + 3 * x0 + c) * wx0 +
                                 __ldg(r1 + 3 * x1 + c) * wx;
                dst[c] = t * wy0 + bt * wy;
            }
        }
    }
    __syncthreads();

    float4* __restrict__ ochunk =
        (float4*)(out + ((((size_t)b * 4 + sc) * HH + yc) * ROWF));
    const float4* __restrict__ srow = (const float4*)rows;
#pragma unroll
    for (int i = 0; i < VPT; i++)
        __stcs(&ochunk[tid + i * NT], srow[tid + i * NT]);
}

extern "C" void kernel_launch(void* const* d_in, const int* in_sizes, int n_in,
                              void* d_out, int out_size) {
    const float* in  = (const float*)d_in[0];
    float*       out = (float*)d_out;
    (void)in_sizes; (void)n_in; (void)out_size;

    msp_kernel<<<N_COMP + N_COPY + N_ZERO, NT>>>(in, out);
}